// round 6
// baseline (speedup 1.0000x reference)
#include <cuda_runtime.h>
#include <cstdint>

// SpherePool: out[bt, no, :] = max_k tensor[bt, index[no, k], :]
// B=2, T=8 (BT=16), N=40962, C=256 fp32, N_OUT=10242, K=7.
//
// Index dtype: reference says int64, but JAX x64 is off by default -> int32
// in practice (Round-2 rel_err 0.948 = reading it as long long). We detect
// the layout at runtime: true little-endian int64 indices (< 2^31) have all
// odd 32-bit words == 0; int32 data essentially never does (p ~ (1/N)^8).
//
// Memory-bound gather. Thread = one float4 (16B) of one output row.
// 64 threads = one full 256-float row -> coalesced 1KB gathers.
// bt-outermost tid ordering keeps each 42MB bt-slice L2-resident for reuse.

static constexpr int BT    = 16;
static constexpr int N_IN  = 40962;
static constexpr int C4    = 64;         // 256 floats / 4 = 64 float4 per row
static constexpr int N_OUT = 10242;
static constexpr int K     = 7;

__global__ __launch_bounds__(256) void sphere_pool_kernel(
    const float4* __restrict__ x,        // [BT, N_IN, C4]
    const int* __restrict__ idx,         // [N_OUT, K] as int32 OR int64 words
    float4* __restrict__ out,            // [BT, N_OUT, C4]
    int total)
{
    int t = blockIdx.x * blockDim.x + threadIdx.x;
    if (t >= total) return;

    int c4   = t & (C4 - 1);
    int rest = t >> 6;                   // / C4
    int no   = rest % N_OUT;
    int bt   = rest / N_OUT;

    // Grid-uniform dtype sniff: odd words of the first 8 "indices".
    // All zero -> int64 layout. These 8 loads are L1-broadcast hits.
    int odd = idx[1] | idx[3] | idx[5] | idx[7] |
              idx[9] | idx[11] | idx[13] | idx[15];
    bool is64 = (odd == 0);

    int i0, i1, i2, i3, i4, i5, i6;
    if (is64) {
        // int64 layout: index j lives at 32-bit word 2*j (little-endian low half)
        const int* ip = idx + (no * K) * 2;
        i0 = ip[0];  i1 = ip[2];  i2 = ip[4];  i3 = ip[6];
        i4 = ip[8];  i5 = ip[10]; i6 = ip[12];
    } else {
        const int* ip = idx + no * K;
        i0 = ip[0]; i1 = ip[1]; i2 = ip[2]; i3 = ip[3];
        i4 = ip[4]; i5 = ip[5]; i6 = ip[6];
    }

    // All offsets fit in int32 (max 16*40962*64 ~= 41.9M elements)
    const float4* base = x + bt * (N_IN * C4) + c4;

    // Issue all 7 gathers up-front: MLP=7 hides DRAM/L2 latency
    float4 v0 = __ldg(base + i0 * C4);
    float4 v1 = __ldg(base + i1 * C4);
    float4 v2 = __ldg(base + i2 * C4);
    float4 v3 = __ldg(base + i3 * C4);
    float4 v4 = __ldg(base + i4 * C4);
    float4 v5 = __ldg(base + i5 * C4);
    float4 v6 = __ldg(base + i6 * C4);

    float4 m;
    m.x = fmaxf(fmaxf(fmaxf(v0.x, v1.x), fmaxf(v2.x, v3.x)),
                fmaxf(fmaxf(v4.x, v5.x), v6.x));
    m.y = fmaxf(fmaxf(fmaxf(v0.y, v1.y), fmaxf(v2.y, v3.y)),
                fmaxf(fmaxf(v4.y, v5.y), v6.y));
    m.z = fmaxf(fmaxf(fmaxf(v0.z, v1.z), fmaxf(v2.z, v3.z)),
                fmaxf(fmaxf(v4.z, v5.z), v6.z));
    m.w = fmaxf(fmaxf(fmaxf(v0.w, v1.w), fmaxf(v2.w, v3.w)),
                fmaxf(fmaxf(v4.w, v5.w), v6.w));

    out[t] = m;
}

extern "C" void kernel_launch(void* const* d_in, const int* in_sizes, int n_in,
                              void* d_out, int out_size)
{
    // Identify inputs by element count instead of assuming order:
    // tensor = 16*40962*256 = 167,780,352 elems; index = 10242*7 = 71,694.
    int ti = 0, ii = 1;
    if (n_in >= 2 && in_sizes[0] < in_sizes[1]) { ti = 1; ii = 0; }

    const float4* x   = (const float4*)d_in[ti];  // tensor fp32
    const int*    idx = (const int*)d_in[ii];     // index words
    float4*       out = (float4*)d_out;

    int total = BT * N_OUT * C4;                  // 10,487,808 threads
    int block = 256;
    int grid  = (total + block - 1) / block;
    sphere_pool_kernel<<<grid, block>>>(x, idx, out, total);
}

// round 9
// speedup vs baseline: 1.0351x; 1.0351x over previous
#include <cuda_runtime.h>
#include <cstdint>

// SpherePool: out[bt, no, :] = max_k tensor[bt, index[no, k], :]
// B=2, T=8 (BT=16), N=40962, C=256 fp32, N_OUT=10242, K=7.
// Index dtype is INT32 (proven: R2 int64-read gave rel_err 0.948; R6 int32
// path gave rel_err 0.0).
//
// R6 ncu: 118.8us, DRAM 75.4%, HBM 5976 GB/s, traffic already compulsory
// (707MB ~= 554MB unique reads + 168MB writes; L2 captures all reuse).
// Remaining lever = achieved BW. occ was 61.8% @ 34 regs -> force 8 blocks/SM
// (regs<=32) for full 64-warp occupancy; drop the dtype sniff; streaming
// stores so output never pollutes the L2 set holding the reusable slice.

static constexpr int BT    = 16;
static constexpr int N_IN  = 40962;
static constexpr int C4    = 64;         // 256 floats / 4 = 64 float4 per row
static constexpr int N_OUT = 10242;
static constexpr int K     = 7;

__global__ __launch_bounds__(256, 8) void sphere_pool_kernel(
    const float4* __restrict__ x,        // [BT, N_IN, C4]
    const int* __restrict__ idx,         // [N_OUT, K] int32
    float4* __restrict__ out,            // [BT, N_OUT, C4]
    int total)
{
    int t = blockIdx.x * blockDim.x + threadIdx.x;
    if (t >= total) return;

    int c4   = t & (C4 - 1);
    int rest = t >> 6;                   // / C4
    int no   = rest % N_OUT;
    int bt   = rest / N_OUT;

    // 7 indices: same addresses across the 64-thread row-group -> L1 broadcast
    const int* ip = idx + no * K;
    int i0 = ip[0];
    int i1 = ip[1];
    int i2 = ip[2];
    int i3 = ip[3];
    int i4 = ip[4];
    int i5 = ip[5];
    int i6 = ip[6];

    // All offsets fit in int32 (max 16*40962*64 ~= 41.9M elements)
    const float4* base = x + bt * (N_IN * C4) + c4;

    // Issue all 7 gathers up-front: MLP=7 hides DRAM/L2 latency
    float4 v0 = __ldg(base + i0 * C4);
    float4 v1 = __ldg(base + i1 * C4);
    float4 v2 = __ldg(base + i2 * C4);
    float4 v3 = __ldg(base + i3 * C4);
    float4 v4 = __ldg(base + i4 * C4);
    float4 v5 = __ldg(base + i5 * C4);
    float4 v6 = __ldg(base + i6 * C4);

    float4 m;
    m.x = fmaxf(fmaxf(fmaxf(v0.x, v1.x), fmaxf(v2.x, v3.x)),
                fmaxf(fmaxf(v4.x, v5.x), v6.x));
    m.y = fmaxf(fmaxf(fmaxf(v0.y, v1.y), fmaxf(v2.y, v3.y)),
                fmaxf(fmaxf(v4.y, v5.y), v6.y));
    m.z = fmaxf(fmaxf(fmaxf(v0.z, v1.z), fmaxf(v2.z, v3.z)),
                fmaxf(fmaxf(v4.z, v5.z), v6.z));
    m.w = fmaxf(fmaxf(fmaxf(v0.w, v1.w), fmaxf(v2.w, v3.w)),
                fmaxf(fmaxf(v4.w, v5.w), v6.w));

    // Streaming store: output is never re-read; evict-first in L2.
    __stcs(&out[t], m);
}

extern "C" void kernel_launch(void* const* d_in, const int* in_sizes, int n_in,
                              void* d_out, int out_size)
{
    // Identify inputs by element count instead of assuming order:
    // tensor = 167,780,352 elems; index = 71,694 elems.
    int ti = 0, ii = 1;
    if (n_in >= 2 && in_sizes[0] < in_sizes[1]) { ti = 1; ii = 0; }

    const float4* x   = (const float4*)d_in[ti];  // tensor fp32
    const int*    idx = (const int*)d_in[ii];     // index int32
    float4*       out = (float4*)d_out;

    int total = BT * N_OUT * C4;                  // 10,487,808 threads
    int block = 256;
    int grid  = (total + block - 1) / block;
    sphere_pool_kernel<<<grid, block>>>(x, idx, out, total);
}